// round 2
// baseline (speedup 1.0000x reference)
#include <cuda_runtime.h>

// Problem constants (fixed shapes)
constexpr int B  = 16;
constexpr int N  = 4096;
constexpr int K  = 32;
constexpr int BN = B * N;   // 65536

// Scratch (device globals; no dynamic allocation allowed)
__device__ float g_frames[BN * 12];  // packed [rot 9 | trans 3] per (b,n), 48B rows
__device__ float g_avg[BN * 12];     // avg_rot 9 + avg_trans 3 per (b,n)

// ---------------------------------------------------------------------------
// Kernel 1: repack frames_rot/frames_trans into 48-byte aligned rows so the
// random gather in kernel 2 is 3x LDG.128 (exactly 2 L2 sectors per gather).
// ---------------------------------------------------------------------------
__global__ void repack_frames_kernel(const float* __restrict__ fr,
                                     const float* __restrict__ ft) {
    int i = blockIdx.x * blockDim.x + threadIdx.x;
    if (i >= BN) return;
    const float* r = fr + (size_t)i * 9;
    const float* t = ft + (size_t)i * 3;
    float4 a = make_float4(r[0], r[1], r[2], r[3]);
    float4 b = make_float4(r[4], r[5], r[6], r[7]);
    float4 c = make_float4(r[8], t[0], t[1], t[2]);
    float4* o = (float4*)(g_frames + (size_t)i * 12);
    o[0] = a; o[1] = b; o[2] = c;
}

// ---------------------------------------------------------------------------
// Kernel 2: one warp per (b,n). Lane k handles neighbor k (K == 32).
// pair_rot/pair_trans staged through shared memory with vectorized loads so
// global traffic is perfectly coalesced; per-lane LDS reads are stride-9 and
// stride-3 words -> conflict-free (gcd(9,32)=gcd(3,32)=1).
// ---------------------------------------------------------------------------
__global__ __launch_bounds__(256) void compose_avg_kernel(
    const float* __restrict__ pair_rot,
    const float* __restrict__ pair_trans,
    const float* __restrict__ conf,
    const int*   __restrict__ topo) {

    __shared__ float sm[8][384];  // per warp: 288 (pair_rot) + 96 (pair_trans)

    int warp = threadIdx.x >> 5;
    int lane = threadIdx.x & 31;
    int wid  = blockIdx.x * 8 + warp;        // (b*N + n)
    int b    = wid >> 12;                    // N = 4096

    // --- stage pair tiles into shared (coalesced float4 loads) ---
    float4* s4 = (float4*)sm[warp];
    const float4* pr4 = (const float4*)(pair_rot + (size_t)wid * 288);
    s4[lane]      = pr4[lane];
    s4[lane + 32] = pr4[lane + 32];
    if (lane < 8) s4[lane + 64] = pr4[lane + 64];
    const float4* pt4 = (const float4*)(pair_trans + (size_t)wid * 96);
    if (lane < 24) s4[72 + lane] = pt4[lane];

    // --- per-lane scalar loads (coalesced) + frame gather ---
    float w = conf[(size_t)wid * K + lane];
    int  j  = topo[(size_t)wid * K + lane];
    const float4* f = (const float4*)(g_frames + ((size_t)(b * N) + j) * 12);
    float4 f0 = f[0], f1 = f[1], f2 = f[2];

    __syncwarp();

    const float* P  = sm[warp] + lane * 9;       // neighbor pair_rot (row-major)
    const float* pt = sm[warp] + 288 + lane * 3; // neighbor pair_trans

    float R0x = f0.x, R0y = f0.y, R0z = f0.z;
    float R1x = f0.w, R1y = f1.x, R1z = f1.y;
    float R2x = f1.z, R2y = f1.w, R2z = f2.x;
    float tx  = f2.y, ty  = f2.z, tz  = f2.w;

    float acc[13];
#pragma unroll
    for (int c = 0; c < 3; c++) {
        float p0 = P[c], p1 = P[3 + c], p2 = P[6 + c];
        acc[0 + c] = w * (R0x * p0 + R0y * p1 + R0z * p2);
        acc[3 + c] = w * (R1x * p0 + R1y * p1 + R1z * p2);
        acc[6 + c] = w * (R2x * p0 + R2y * p1 + R2z * p2);
    }
    {
        float q0 = pt[0], q1 = pt[1], q2 = pt[2];
        acc[9]  = w * (R0x * q0 + R0y * q1 + R0z * q2 + tx);
        acc[10] = w * (R1x * q0 + R1y * q1 + R1z * q2 + ty);
        acc[11] = w * (R2x * q0 + R2y * q1 + R2z * q2 + tz);
    }
    acc[12] = w;

    // --- butterfly reduce all 13 values across the warp ---
#pragma unroll
    for (int i = 0; i < 13; i++) {
#pragma unroll
        for (int off = 16; off; off >>= 1)
            acc[i] += __shfl_xor_sync(0xffffffffu, acc[i], off);
    }

    if (lane == 0) {
        float inv = __fdividef(1.0f, acc[12]);
        float4* o = (float4*)(g_avg + (size_t)wid * 12);
        o[0] = make_float4(acc[0] * inv, acc[1] * inv, acc[2]  * inv, acc[3]  * inv);
        o[1] = make_float4(acc[4] * inv, acc[5] * inv, acc[6]  * inv, acc[7]  * inv);
        o[2] = make_float4(acc[8] * inv, acc[9] * inv, acc[10] * inv, acc[11] * inv);
    }
}

// ---------------------------------------------------------------------------
// Kernel 3: one thread per (b,n). Project avg_rot onto SO(3) (det=+1) via
// Jacobi eigendecomposition of A^T A, then R = U V^T with u3 = u1 x u2 and
// det(V)=+1 enforced. This equals the reference's rot_inv = u diag(1,1,d) vh.
// ---------------------------------------------------------------------------
template <int p, int q, int r>
__device__ __forceinline__ void jrot(float S[3][3], float V[3][3]) {
    float spq = S[p][q];
    if (fabsf(spq) > 1e-30f) {
        float tau = (S[q][q] - S[p][p]) / (2.0f * spq);
        float t   = copysignf(1.0f, tau) / (fabsf(tau) + sqrtf(1.0f + tau * tau));
        float c   = rsqrtf(1.0f + t * t);
        float s   = t * c;
        float spp = S[p][p], sqq = S[q][q];
        S[p][p] = spp - t * spq;
        S[q][q] = sqq + t * spq;
        S[p][q] = 0.0f; S[q][p] = 0.0f;
        float srp = S[r][p], srq = S[r][q];
        S[r][p] = c * srp - s * srq; S[p][r] = S[r][p];
        S[r][q] = s * srp + c * srq; S[q][r] = S[r][q];
#pragma unroll
        for (int i = 0; i < 3; i++) {
            float vip = V[i][p], viq = V[i][q];
            V[i][p] = c * vip - s * viq;
            V[i][q] = s * vip + c * viq;
        }
    }
}

__global__ __launch_bounds__(256) void svd_project_kernel(float* __restrict__ out) {
    int i = blockIdx.x * blockDim.x + threadIdx.x;
    if (i >= BN) return;

    const float4* m = (const float4*)(g_avg + (size_t)i * 12);
    float4 m0 = m[0], m1 = m[1], m2 = m[2];
    // A row-major
    float a[3][3] = {{m0.x, m0.y, m0.z},
                     {m0.w, m1.x, m1.y},
                     {m1.z, m1.w, m2.x}};
    float t0 = m2.y, t1 = m2.z, t2 = m2.w;

    // S = A^T A (symmetric)
    float S[3][3];
#pragma unroll
    for (int c = 0; c < 3; c++)
#pragma unroll
        for (int d = c; d < 3; d++) {
            float v = a[0][c] * a[0][d] + a[1][c] * a[1][d] + a[2][c] * a[2][d];
            S[c][d] = v; S[d][c] = v;
        }

    float V[3][3] = {{1, 0, 0}, {0, 1, 0}, {0, 0, 1}};
#pragma unroll
    for (int sweep = 0; sweep < 5; sweep++) {
        jrot<0, 1, 2>(S, V);
        jrot<0, 2, 1>(S, V);
        jrot<1, 2, 0>(S, V);
    }

    // eigenpairs (columns of V), sort descending by eigenvalue
    float l0 = S[0][0], l1 = S[1][1], l2 = S[2][2];
    float v0x = V[0][0], v0y = V[1][0], v0z = V[2][0];
    float v1x = V[0][1], v1y = V[1][1], v1z = V[2][1];
    float v2x = V[0][2], v2y = V[1][2], v2z = V[2][2];

#define CSWAP(la, lb, ax, ay, az, bx, by, bz)                                  \
    if (la < lb) {                                                             \
        float tmp;                                                             \
        tmp = la; la = lb; lb = tmp;                                           \
        tmp = ax; ax = bx; bx = tmp;                                           \
        tmp = ay; ay = by; by = tmp;                                           \
        tmp = az; az = bz; bz = tmp;                                           \
    }
    CSWAP(l0, l1, v0x, v0y, v0z, v1x, v1y, v1z)
    CSWAP(l0, l2, v0x, v0y, v0z, v2x, v2y, v2z)
    CSWAP(l1, l2, v1x, v1y, v1z, v2x, v2y, v2z)
#undef CSWAP

    // enforce det([v0 v1 v2]) = +1
    float cx = v1y * v2z - v1z * v2y;
    float cy = v1z * v2x - v1x * v2z;
    float cz = v1x * v2y - v1y * v2x;
    float det = v0x * cx + v0y * cy + v0z * cz;
    if (det < 0.0f) { v2x = -v2x; v2y = -v2y; v2z = -v2z; }

    // u0 = normalize(A v0)
    float u0x = a[0][0] * v0x + a[0][1] * v0y + a[0][2] * v0z;
    float u0y = a[1][0] * v0x + a[1][1] * v0y + a[1][2] * v0z;
    float u0z = a[2][0] * v0x + a[2][1] * v0y + a[2][2] * v0z;
    float inv0 = rsqrtf(u0x * u0x + u0y * u0y + u0z * u0z + 1e-30f);
    u0x *= inv0; u0y *= inv0; u0z *= inv0;

    // u1 = normalize(GramSchmidt(A v1, u0))
    float u1x = a[0][0] * v1x + a[0][1] * v1y + a[0][2] * v1z;
    float u1y = a[1][0] * v1x + a[1][1] * v1y + a[1][2] * v1z;
    float u1z = a[2][0] * v1x + a[2][1] * v1y + a[2][2] * v1z;
    float dp = u0x * u1x + u0y * u1y + u0z * u1z;
    u1x -= dp * u0x; u1y -= dp * u0y; u1z -= dp * u0z;
    float inv1 = rsqrtf(u1x * u1x + u1y * u1y + u1z * u1z + 1e-30f);
    u1x *= inv1; u1y *= inv1; u1z *= inv1;

    // u2 = u0 x u1 (det(U) = +1)
    float u2x = u0y * u1z - u0z * u1y;
    float u2y = u0z * u1x - u0x * u1z;
    float u2z = u0x * u1y - u0y * u1x;

    // R = u0 v0^T + u1 v1^T + u2 v2^T  (this IS rot_inv of the reference)
    float R00 = u0x * v0x + u1x * v1x + u2x * v2x;
    float R01 = u0x * v0y + u1x * v1y + u2x * v2y;
    float R02 = u0x * v0z + u1x * v1z + u2x * v2z;
    float R10 = u0y * v0x + u1y * v1x + u2y * v2x;
    float R11 = u0y * v0y + u1y * v1y + u2y * v2y;
    float R12 = u0y * v0z + u1y * v1z + u2y * v2z;
    float R20 = u0z * v0x + u1z * v1x + u2z * v2x;
    float R21 = u0z * v0y + u1z * v1y + u2z * v2y;
    float R22 = u0z * v0z + u1z * v1z + u2z * v2z;

    float4* o = (float4*)(out + (size_t)i * 12);
    o[0] = make_float4(R00, R01, R02, R10);
    o[1] = make_float4(R11, R12, R20, R21);
    o[2] = make_float4(R22, t0, t1, t2);
}

// ---------------------------------------------------------------------------
extern "C" void kernel_launch(void* const* d_in, const int* in_sizes, int n_in,
                              void* d_out, int out_size) {
    const float* frames_rot   = (const float*)d_in[0];
    const float* frames_trans = (const float*)d_in[1];
    const float* pair_rot     = (const float*)d_in[2];
    const float* pair_trans   = (const float*)d_in[3];
    const float* confidences  = (const float*)d_in[4];
    const int*   topology     = (const int*)d_in[5];
    float*       out          = (float*)d_out;

    repack_frames_kernel<<<BN / 256, 256>>>(frames_rot, frames_trans);
    compose_avg_kernel<<<BN / 8, 256>>>(pair_rot, pair_trans, confidences, topology);
    svd_project_kernel<<<BN / 256, 256>>>(out);
}

// round 3
// speedup vs baseline: 1.1651x; 1.1651x over previous
#include <cuda_runtime.h>

// Problem constants (fixed shapes)
constexpr int B  = 16;
constexpr int N  = 4096;
constexpr int K  = 32;
constexpr int BN = B * N;   // 65536

// Scratch (device globals; no dynamic allocation allowed)
__device__ float g_frames[BN * 12];  // packed [rot 9 | trans 3] per (b,n), 48B rows
__device__ float g_avg[BN * 12];     // avg_rot 9 + avg_trans 3 per (b,n)

// ---------------------------------------------------------------------------
// Kernel 1: repack frames into 48-byte rows. One float per thread, fully
// coalesced read and write (monotonic addresses on both sides).
// ---------------------------------------------------------------------------
__global__ void repack_frames_kernel(const float* __restrict__ fr,
                                     const float* __restrict__ ft) {
    int m = blockIdx.x * 256 + threadIdx.x;      // 0 .. BN*12-1
    if (m >= BN * 12) return;
    int i = m / 12;
    int c = m - i * 12;
    float v = (c < 9) ? fr[i * 9 + c] : ft[i * 3 + (c - 9)];
    g_frames[m] = v;
}

// ---------------------------------------------------------------------------
// Kernel 2: 4 (b,n) per warp; 8 lanes per (b,n); lane (g,s) handles neighbors
// k = s + 8i (i=0..3) of tile g. Smem tiles padded so tile stride ≡ 8 (mod 32)
// floats -> strided scalar LDS reads are bank-conflict-free, while vector STS
// staging stays 16B-aligned. Reduction: 3 butterfly steps over 8-lane groups.
// ---------------------------------------------------------------------------
constexpr int TSR = 296;                  // rot tile stride (floats), 296%32==8
constexpr int TST = 104;                  // trans tile stride (floats), 104%32==8
constexpr int WSM = 4 * TSR + 4 * TST;    // 1600 floats per warp
constexpr int WARPS_PER_BLOCK = 6;        // 192 threads; 38.4 KB static smem

__global__ __launch_bounds__(192) void compose_avg_kernel(
    const float* __restrict__ pair_rot,
    const float* __restrict__ pair_trans,
    const float* __restrict__ conf,
    const int*   __restrict__ topo) {

    __shared__ float sm[WARPS_PER_BLOCK * WSM];

    int warp = threadIdx.x >> 5;
    int lane = threadIdx.x & 31;
    int g    = lane >> 3;                 // tile within warp (0..3)
    int s    = lane & 7;                  // sub-lane within tile (0..7)
    int bn0  = (blockIdx.x * WARPS_PER_BLOCK + warp) * 4;
    if (bn0 >= BN) return;                // uniform per warp
    int bn   = bn0 + g;
    int b    = bn >> 12;                  // N = 4096

    float* W   = sm + warp * WSM;
    float* ROT = W;                       // 4 tiles at g*TSR
    float* TRN = W + 4 * TSR;             // 4 tiles at g*TST

    // --- stage pair_rot: 4 tiles x 288 floats = 288 float4, padded tiles ---
    {
        const float4* prg = (const float4*)pair_rot + (size_t)bn0 * 72;
        float4* rf4 = (float4*)ROT;
#pragma unroll
        for (int q = 0; q < 9; q++) {
            int f = q * 32 + lane;        // 0..287
            int t = f / 72;
            int w = f - t * 72;
            rf4[t * 74 + w] = prg[f];     // 74 float4 = 296 floats per tile
        }
    }
    // --- stage pair_trans: 4 tiles x 96 floats = 96 float4 ---
    {
        const float4* ptg = (const float4*)pair_trans + (size_t)bn0 * 24;
        float4* tf4 = (float4*)TRN;
#pragma unroll
        for (int q = 0; q < 3; q++) {
            int f = q * 32 + lane;        // 0..95
            int t = f / 24;
            int w = f - t * 24;
            tf4[t * 26 + w] = ptg[f];     // 26 float4 = 104 floats per tile
        }
    }

    // --- conf & topo for this lane's 4 neighbors (strided scalar loads) ---
    const float* cfb = conf + (size_t)bn * K;
    const int*   tpb = topo + (size_t)bn * K;
    float wgt[4];
    int   jj[4];
#pragma unroll
    for (int i = 0; i < 4; i++) {
        wgt[i] = cfb[s + 8 * i];
        jj[i]  = tpb[s + 8 * i];
    }

    __syncwarp();

    const float* fbase = g_frames + (size_t)(b << 12) * 12;

    float acc[13];
#pragma unroll
    for (int v = 0; v < 13; v++) acc[v] = 0.0f;

#pragma unroll
    for (int i = 0; i < 4; i++) {
        int k = s + 8 * i;
        const float4* F = (const float4*)(fbase + (size_t)jj[i] * 12);
        float4 f0 = F[0], f1 = F[1], f2 = F[2];

        const float* P = ROT + g * TSR + k * 9;   // conflict-free scalar LDS
        const float* Q = TRN + g * TST + k * 3;

        float w = wgt[i];
        float R0x = f0.x, R0y = f0.y, R0z = f0.z;
        float R1x = f0.w, R1y = f1.x, R1z = f1.y;
        float R2x = f1.z, R2y = f1.w, R2z = f2.x;
        float tx  = f2.y, ty  = f2.z, tz  = f2.w;

#pragma unroll
        for (int c = 0; c < 3; c++) {
            float p0 = P[c], p1 = P[3 + c], p2 = P[6 + c];
            acc[0 + c] += w * (R0x * p0 + R0y * p1 + R0z * p2);
            acc[3 + c] += w * (R1x * p0 + R1y * p1 + R1z * p2);
            acc[6 + c] += w * (R2x * p0 + R2y * p1 + R2z * p2);
        }
        float q0 = Q[0], q1 = Q[1], q2 = Q[2];
        acc[9]  += w * (R0x * q0 + R0y * q1 + R0z * q2 + tx);
        acc[10] += w * (R1x * q0 + R1y * q1 + R1z * q2 + ty);
        acc[11] += w * (R2x * q0 + R2y * q1 + R2z * q2 + tz);
        acc[12] += w;
    }

    // --- butterfly reduce across the 8-lane group (xor 4,2,1) ---
#pragma unroll
    for (int v = 0; v < 13; v++) {
        acc[v] += __shfl_xor_sync(0xffffffffu, acc[v], 4);
        acc[v] += __shfl_xor_sync(0xffffffffu, acc[v], 2);
        acc[v] += __shfl_xor_sync(0xffffffffu, acc[v], 1);
    }

    if (s == 0) {
        float inv = __fdividef(1.0f, acc[12]);
        float4* o = (float4*)(g_avg + (size_t)bn * 12);
        o[0] = make_float4(acc[0] * inv, acc[1] * inv, acc[2]  * inv, acc[3]  * inv);
        o[1] = make_float4(acc[4] * inv, acc[5] * inv, acc[6]  * inv, acc[7]  * inv);
        o[2] = make_float4(acc[8] * inv, acc[9] * inv, acc[10] * inv, acc[11] * inv);
    }
}

// ---------------------------------------------------------------------------
// Kernel 3: one thread per (b,n). Jacobi SVD projection onto SO(3), same as
// the passing round-2 version.
// ---------------------------------------------------------------------------
template <int p, int q, int r>
__device__ __forceinline__ void jrot(float S[3][3], float V[3][3]) {
    float spq = S[p][q];
    if (fabsf(spq) > 1e-30f) {
        float tau = (S[q][q] - S[p][p]) / (2.0f * spq);
        float t   = copysignf(1.0f, tau) / (fabsf(tau) + sqrtf(1.0f + tau * tau));
        float c   = rsqrtf(1.0f + t * t);
        float s   = t * c;
        float spp = S[p][p], sqq = S[q][q];
        S[p][p] = spp - t * spq;
        S[q][q] = sqq + t * spq;
        S[p][q] = 0.0f; S[q][p] = 0.0f;
        float srp = S[r][p], srq = S[r][q];
        S[r][p] = c * srp - s * srq; S[p][r] = S[r][p];
        S[r][q] = s * srp + c * srq; S[q][r] = S[r][q];
#pragma unroll
        for (int i = 0; i < 3; i++) {
            float vip = V[i][p], viq = V[i][q];
            V[i][p] = c * vip - s * viq;
            V[i][q] = s * vip + c * viq;
        }
    }
}

__global__ __launch_bounds__(256) void svd_project_kernel(float* __restrict__ out) {
    int i = blockIdx.x * blockDim.x + threadIdx.x;
    if (i >= BN) return;

    const float4* m = (const float4*)(g_avg + (size_t)i * 12);
    float4 m0 = m[0], m1 = m[1], m2 = m[2];
    float a[3][3] = {{m0.x, m0.y, m0.z},
                     {m0.w, m1.x, m1.y},
                     {m1.z, m1.w, m2.x}};
    float t0 = m2.y, t1 = m2.z, t2 = m2.w;

    float S[3][3];
#pragma unroll
    for (int c = 0; c < 3; c++)
#pragma unroll
        for (int d = c; d < 3; d++) {
            float v = a[0][c] * a[0][d] + a[1][c] * a[1][d] + a[2][c] * a[2][d];
            S[c][d] = v; S[d][c] = v;
        }

    float V[3][3] = {{1, 0, 0}, {0, 1, 0}, {0, 0, 1}};
#pragma unroll
    for (int sweep = 0; sweep < 5; sweep++) {
        jrot<0, 1, 2>(S, V);
        jrot<0, 2, 1>(S, V);
        jrot<1, 2, 0>(S, V);
    }

    float l0 = S[0][0], l1 = S[1][1], l2 = S[2][2];
    float v0x = V[0][0], v0y = V[1][0], v0z = V[2][0];
    float v1x = V[0][1], v1y = V[1][1], v1z = V[2][1];
    float v2x = V[0][2], v2y = V[1][2], v2z = V[2][2];

#define CSWAP(la, lb, ax, ay, az, bx, by, bz)                                  \
    if (la < lb) {                                                             \
        float tmp;                                                             \
        tmp = la; la = lb; lb = tmp;                                           \
        tmp = ax; ax = bx; bx = tmp;                                           \
        tmp = ay; ay = by; by = tmp;                                           \
        tmp = az; az = bz; bz = tmp;                                           \
    }
    CSWAP(l0, l1, v0x, v0y, v0z, v1x, v1y, v1z)
    CSWAP(l0, l2, v0x, v0y, v0z, v2x, v2y, v2z)
    CSWAP(l1, l2, v1x, v1y, v1z, v2x, v2y, v2z)
#undef CSWAP

    float cx = v1y * v2z - v1z * v2y;
    float cy = v1z * v2x - v1x * v2z;
    float cz = v1x * v2y - v1y * v2x;
    float det = v0x * cx + v0y * cy + v0z * cz;
    if (det < 0.0f) { v2x = -v2x; v2y = -v2y; v2z = -v2z; }

    float u0x = a[0][0] * v0x + a[0][1] * v0y + a[0][2] * v0z;
    float u0y = a[1][0] * v0x + a[1][1] * v0y + a[1][2] * v0z;
    float u0z = a[2][0] * v0x + a[2][1] * v0y + a[2][2] * v0z;
    float inv0 = rsqrtf(u0x * u0x + u0y * u0y + u0z * u0z + 1e-30f);
    u0x *= inv0; u0y *= inv0; u0z *= inv0;

    float u1x = a[0][0] * v1x + a[0][1] * v1y + a[0][2] * v1z;
    float u1y = a[1][0] * v1x + a[1][1] * v1y + a[1][2] * v1z;
    float u1z = a[2][0] * v1x + a[2][1] * v1y + a[2][2] * v1z;
    float dp = u0x * u1x + u0y * u1y + u0z * u1z;
    u1x -= dp * u0x; u1y -= dp * u0y; u1z -= dp * u0z;
    float inv1 = rsqrtf(u1x * u1x + u1y * u1y + u1z * u1z + 1e-30f);
    u1x *= inv1; u1y *= inv1; u1z *= inv1;

    float u2x = u0y * u1z - u0z * u1y;
    float u2y = u0z * u1x - u0x * u1z;
    float u2z = u0x * u1y - u0y * u1x;

    float R00 = u0x * v0x + u1x * v1x + u2x * v2x;
    float R01 = u0x * v0y + u1x * v1y + u2x * v2y;
    float R02 = u0x * v0z + u1x * v1z + u2x * v2z;
    float R10 = u0y * v0x + u1y * v1x + u2y * v2x;
    float R11 = u0y * v0y + u1y * v1y + u2y * v2y;
    float R12 = u0y * v0z + u1y * v1z + u2y * v2z;
    float R20 = u0z * v0x + u1z * v1x + u2z * v2x;
    float R21 = u0z * v0y + u1z * v1y + u2z * v2y;
    float R22 = u0z * v0z + u1z * v1z + u2z * v2z;

    float4* o = (float4*)(out + (size_t)i * 12);
    o[0] = make_float4(R00, R01, R02, R10);
    o[1] = make_float4(R11, R12, R20, R21);
    o[2] = make_float4(R22, t0, t1, t2);
}

// ---------------------------------------------------------------------------
extern "C" void kernel_launch(void* const* d_in, const int* in_sizes, int n_in,
                              void* d_out, int out_size) {
    const float* frames_rot   = (const float*)d_in[0];
    const float* frames_trans = (const float*)d_in[1];
    const float* pair_rot     = (const float*)d_in[2];
    const float* pair_trans   = (const float*)d_in[3];
    const float* confidences  = (const float*)d_in[4];
    const int*   topology     = (const int*)d_in[5];
    float*       out          = (float*)d_out;

    repack_frames_kernel<<<(BN * 12) / 256, 256>>>(frames_rot, frames_trans);

    int bn_per_block = WARPS_PER_BLOCK * 4;
    int grid = (BN + bn_per_block - 1) / bn_per_block;
    compose_avg_kernel<<<grid, WARPS_PER_BLOCK * 32>>>(pair_rot, pair_trans,
                                                       confidences, topology);

    svd_project_kernel<<<BN / 256, 256>>>(out);
}